// round 1
// baseline (speedup 1.0000x reference)
#include <cuda_runtime.h>
#include <cstdint>
#include <cstddef>
#include <math_constants.h>

#define NROWS     16384
#define NCODES    8192
#define DIM       256
#define ZQ_ELEMS  4194304     /* NROWS*DIM */
#define LOSS_OFF  4194304
#define CODES_OFF 4194305

// 512 MB scratch: holds fp32 logits, then overwritten in-place with softmax weights.
static __device__ float  g_logits[(size_t)NROWS * NCODES];
static __device__ float  g_kl[NROWS];
static __device__ double g_part[4096];

// ---------------------------------------------------------------------------
// Threefry-2x32 (20 rounds), key = threefry_seed(42) = (0, 42)
// ---------------------------------------------------------------------------
__device__ __forceinline__ void threefry2x32(uint32_t x0, uint32_t x1,
                                             uint32_t& o0, uint32_t& o1) {
  const uint32_t ks0 = 0u;
  const uint32_t ks1 = 42u;
  const uint32_t ks2 = 0x1BD11BDAu ^ ks0 ^ ks1;
  x0 += ks0; x1 += ks1;
#define TF_R(r) { x0 += x1; x1 = __funnelshift_l(x1, x1, (r)); x1 ^= x0; }
  TF_R(13) TF_R(15) TF_R(26) TF_R(6)
  x0 += ks1; x1 += ks2 + 1u;
  TF_R(17) TF_R(29) TF_R(16) TF_R(24)
  x0 += ks2; x1 += ks0 + 2u;
  TF_R(13) TF_R(15) TF_R(26) TF_R(6)
  x0 += ks0; x1 += ks1 + 3u;
  TF_R(17) TF_R(29) TF_R(16) TF_R(24)
  x0 += ks1; x1 += ks2 + 4u;
  TF_R(13) TF_R(15) TF_R(26) TF_R(6)
  x0 += ks2; x1 += ks0 + 5u;
#undef TF_R
  o0 = x0; o1 = x1;
}

// jax_threefry_partitionable=True path (modern JAX default):
// per-element uint64 counter -> (hi=0, lo=idx); 32-bit draw = out0 ^ out1.
// uniform: f = bitcast(bits>>9 | 0x3f800000) - 1;  u = max(tiny, f*(1-tiny)+tiny)
// gumbel:  g = -log(-log(u))
__device__ __forceinline__ float gumbel_at(uint32_t idx) {
  uint32_t o0, o1;
  threefry2x32(0u, idx, o0, o1);
  uint32_t bits = o0 ^ o1;
  float f = __uint_as_float((bits >> 9) | 0x3f800000u) - 1.0f;
  float u = fmaxf(1.17549435e-38f, f + 1.17549435e-38f);
  return -logf(-logf(u));
}

// ---------------------------------------------------------------------------
// GEMM NT: C[m,n] = sum_k A[m*K+k] * B[n*K+k]   (logits = z @ codebook^T)
// 128x128 tile, BK=16, 256 threads, 8x8 per thread
// ---------------------------------------------------------------------------
__global__ __launch_bounds__(256, 2) void gemm_nt_kernel(
    const float* __restrict__ A, const float* __restrict__ B,
    float* __restrict__ C, int M, int N, int K)
{
  __shared__ float As[16][132];
  __shared__ float Bs[16][132];
  const int bm = blockIdx.y * 128;
  const int bn = blockIdx.x * 128;
  const int t  = threadIdx.x;
  const int tx = t & 15;
  const int ty = t >> 4;

  float acc[8][8];
#pragma unroll
  for (int i = 0; i < 8; ++i)
#pragma unroll
    for (int j = 0; j < 8; ++j) acc[i][j] = 0.0f;

  for (int k0 = 0; k0 < K; k0 += 16) {
#pragma unroll
    for (int i = 0; i < 2; ++i) {
      int idx = t + i * 256;
      int row = idx >> 2;
      int kq  = (idx & 3) << 2;
      float4 va = *(const float4*)(A + (size_t)(bm + row) * K + k0 + kq);
      As[kq + 0][row] = va.x;
      As[kq + 1][row] = va.y;
      As[kq + 2][row] = va.z;
      As[kq + 3][row] = va.w;
      float4 vb = *(const float4*)(B + (size_t)(bn + row) * K + k0 + kq);
      Bs[kq + 0][row] = vb.x;
      Bs[kq + 1][row] = vb.y;
      Bs[kq + 2][row] = vb.z;
      Bs[kq + 3][row] = vb.w;
    }
    __syncthreads();
#pragma unroll
    for (int kk = 0; kk < 16; ++kk) {
      float a[8], b[8];
      *(float4*)(a)     = *(const float4*)(&As[kk][ty * 8]);
      *(float4*)(a + 4) = *(const float4*)(&As[kk][ty * 8 + 4]);
      *(float4*)(b)     = *(const float4*)(&Bs[kk][tx * 8]);
      *(float4*)(b + 4) = *(const float4*)(&Bs[kk][tx * 8 + 4]);
#pragma unroll
      for (int i = 0; i < 8; ++i)
#pragma unroll
        for (int j = 0; j < 8; ++j)
          acc[i][j] = fmaf(a[i], b[j], acc[i][j]);
    }
    __syncthreads();
  }
#pragma unroll
  for (int i = 0; i < 8; ++i) {
    float* cp = C + (size_t)(bm + ty * 8 + i) * N + bn + tx * 8;
    *(float4*)(cp)     = make_float4(acc[i][0], acc[i][1], acc[i][2], acc[i][3]);
    *(float4*)(cp + 4) = make_float4(acc[i][4], acc[i][5], acc[i][6], acc[i][7]);
  }
}

// ---------------------------------------------------------------------------
// GEMM NN: C[m,n] = sum_k A[m*K+k] * B[k*N+n]   (z_q = W @ codebook)
// ---------------------------------------------------------------------------
__global__ __launch_bounds__(256, 2) void gemm_nn_kernel(
    const float* __restrict__ A, const float* __restrict__ B,
    float* __restrict__ C, int M, int N, int K)
{
  __shared__ float As[16][132];
  __shared__ float Bs[16][132];
  const int bm = blockIdx.y * 128;
  const int bn = blockIdx.x * 128;
  const int t  = threadIdx.x;
  const int tx = t & 15;
  const int ty = t >> 4;

  float acc[8][8];
#pragma unroll
  for (int i = 0; i < 8; ++i)
#pragma unroll
    for (int j = 0; j < 8; ++j) acc[i][j] = 0.0f;

  for (int k0 = 0; k0 < K; k0 += 16) {
#pragma unroll
    for (int i = 0; i < 2; ++i) {
      int idx = t + i * 256;
      int row = idx >> 2;
      int kq  = (idx & 3) << 2;
      float4 va = *(const float4*)(A + (size_t)(bm + row) * K + k0 + kq);
      As[kq + 0][row] = va.x;
      As[kq + 1][row] = va.y;
      As[kq + 2][row] = va.z;
      As[kq + 3][row] = va.w;
      int kr = idx >> 5;
      int nc = (idx & 31) << 2;
      *(float4*)(&Bs[kr][nc]) =
          *(const float4*)(B + (size_t)(k0 + kr) * N + bn + nc);
    }
    __syncthreads();
#pragma unroll
    for (int kk = 0; kk < 16; ++kk) {
      float a[8], b[8];
      *(float4*)(a)     = *(const float4*)(&As[kk][ty * 8]);
      *(float4*)(a + 4) = *(const float4*)(&As[kk][ty * 8 + 4]);
      *(float4*)(b)     = *(const float4*)(&Bs[kk][tx * 8]);
      *(float4*)(b + 4) = *(const float4*)(&Bs[kk][tx * 8 + 4]);
#pragma unroll
      for (int i = 0; i < 8; ++i)
#pragma unroll
        for (int j = 0; j < 8; ++j)
          acc[i][j] = fmaf(a[i], b[j], acc[i][j]);
    }
    __syncthreads();
  }
#pragma unroll
  for (int i = 0; i < 8; ++i) {
    float* cp = C + (size_t)(bm + ty * 8 + i) * N + bn + tx * 8;
    *(float4*)(cp)     = make_float4(acc[i][0], acc[i][1], acc[i][2], acc[i][3]);
    *(float4*)(cp + 4) = make_float4(acc[i][4], acc[i][5], acc[i][6], acc[i][7]);
  }
}

// ---------------------------------------------------------------------------
// Per-row: gumbel noise, two softmax stats, argmax, KL row-sum.
// Overwrites logits row with gumbel-softmax weights. One CTA per row.
// ---------------------------------------------------------------------------
__global__ __launch_bounds__(256) void row_kernel(float* __restrict__ logits,
                                                  float* __restrict__ out)
{
  __shared__ float redf[256];
  __shared__ float redg[256];
  __shared__ int   redi[256];

  const int row = blockIdx.x;
  const int t   = threadIdx.x;
  float* __restrict__ lrow = logits + (size_t)row * NCODES;
  const uint32_t base = (uint32_t)row * (uint32_t)NCODES;

  float lv[32], yv[32];
  float bestl = -CUDART_INF_F;
  int   besti = 0;
  float m2 = -CUDART_INF_F;

#pragma unroll
  for (int i = 0; i < 32; ++i) {
    int c = i * 256 + t;
    float l = lrow[c];
    float g = gumbel_at(base + (uint32_t)c);
    float y = l + g;                 // tau = 1.0
    lv[i] = l;
    yv[i] = y;
    if (l > bestl) { bestl = l; besti = c; }
    m2 = fmaxf(m2, y);
  }

  redf[t] = bestl; redi[t] = besti; redg[t] = m2;
  __syncthreads();
  for (int s = 128; s > 0; s >>= 1) {
    if (t < s) {
      float v = redf[t + s]; int vi = redi[t + s];
      if (v > redf[t] || (v == redf[t] && vi < redi[t])) { redf[t] = v; redi[t] = vi; }
      redg[t] = fmaxf(redg[t], redg[t + s]);
    }
    __syncthreads();
  }
  const float M1 = redf[0];
  const int   AM = redi[0];
  const float M2 = redg[0];
  __syncthreads();

  float z1 = 0.0f, z2 = 0.0f;
#pragma unroll
  for (int i = 0; i < 32; ++i) {
    z1 += expf(lv[i] - M1);
    z2 += expf(yv[i] - M2);
  }
  redf[t] = z1; redg[t] = z2;
  __syncthreads();
  for (int s = 128; s > 0; s >>= 1) {
    if (t < s) { redf[t] += redf[t + s]; redg[t] += redg[t + s]; }
    __syncthreads();
  }
  const float lZ1 = logf(redf[0]);
  const float rZ2 = 1.0f / redg[0];
  __syncthreads();

  float kl = 0.0f;
#pragma unroll
  for (int i = 0; i < 32; ++i) {
    int c = i * 256 + t;
    float sh = lv[i] - M1;
    float q  = expf(sh - lZ1);                       // qy = exp(log_softmax)
    kl += q * logf(q * 8192.0f + 1e-10f);
    lrow[c] = expf(yv[i] - M2) * rZ2;                // gumbel-softmax weight
  }
  redf[t] = kl;
  __syncthreads();
  for (int s = 128; s > 0; s >>= 1) {
    if (t < s) redf[t] += redf[t + s];
    __syncthreads();
  }
  if (t == 0) {
    g_kl[row] = redf[0];
    out[CODES_OFF + row] = (float)AM;
  }
}

// ---------------------------------------------------------------------------
// Straight-through + commit-loss partial sums. z_q already in out[0:ZQ_ELEMS].
// ---------------------------------------------------------------------------
__global__ __launch_bounds__(256) void st_commit_kernel(const float* __restrict__ z,
                                                        float* __restrict__ out)
{
  __shared__ double red[256];
  const int t = threadIdx.x;
  const size_t i4 = ((size_t)blockIdx.x * 256 + t) * 4;
  float4 zq = *(const float4*)(out + i4);
  float4 zv = *(const float4*)(z + i4);
  float dx = zq.x - zv.x;
  float dy = zq.y - zv.y;
  float dz = zq.z - zv.z;
  float dw = zq.w - zv.w;
  // z_q_st = z + (z_q - z), matching reference rounding
  *(float4*)(out + i4) = make_float4(zv.x + dx, zv.y + dy, zv.z + dz, zv.w + dw);
  red[t] = (double)(dx * dx) + (double)(dy * dy) +
           (double)(dz * dz) + (double)(dw * dw);
  __syncthreads();
  for (int s = 128; s > 0; s >>= 1) {
    if (t < s) red[t] += red[t + s];
    __syncthreads();
  }
  if (t == 0) g_part[blockIdx.x] = red[0];
}

__global__ __launch_bounds__(256) void finalize_kernel(float* __restrict__ out)
{
  __shared__ double red[256];
  const int t = threadIdx.x;

  double cs = 0.0;
  for (int i = t; i < 4096; i += 256) cs += g_part[i];
  red[t] = cs;
  __syncthreads();
  for (int s = 128; s > 0; s >>= 1) { if (t < s) red[t] += red[t + s]; __syncthreads(); }
  const double commit_sum = red[0];
  __syncthreads();

  double ks = 0.0;
  for (int i = t; i < NROWS; i += 256) ks += (double)g_kl[i];
  red[t] = ks;
  __syncthreads();
  for (int s = 128; s > 0; s >>= 1) { if (t < s) red[t] += red[t + s]; __syncthreads(); }

  if (t == 0) {
    float commit = 0.25f * (float)(commit_sum / (double)ZQ_ELEMS);
    float klm    = 0.01f * (float)(red[0] / (double)NROWS);
    out[LOSS_OFF] = commit + klm;
  }
}

// ---------------------------------------------------------------------------
extern "C" void kernel_launch(void* const* d_in, const int* in_sizes, int n_in,
                              void* d_out, int out_size)
{
  const float* z  = (const float*)d_in[0];
  const float* cb = (const float*)d_in[1];
  float* out = (float*)d_out;

  void* sym = nullptr;
  cudaGetSymbolAddress(&sym, g_logits);
  float* logits = (float*)sym;

  dim3 g1(NCODES / 128, NROWS / 128);           // 64 x 128
  gemm_nt_kernel<<<g1, 256>>>(z, cb, logits, NROWS, NCODES, DIM);

  row_kernel<<<NROWS, 256>>>(logits, out);

  dim3 g2(DIM / 128, NROWS / 128);              // 2 x 128
  gemm_nn_kernel<<<g2, 256>>>(logits, cb, out, NROWS, DIM, NCODES);

  st_commit_kernel<<<ZQ_ELEMS / 1024, 256>>>(z, out);
  finalize_kernel<<<1, 256>>>(out);
}

// round 2
// speedup vs baseline: 1.0007x; 1.0007x over previous
#include <cuda_runtime.h>
#include <cstdint>
#include <cstddef>
#include <math_constants.h>

#define NROWS     16384
#define NCODES    8192
#define DIM       256
#define ZQ_ELEMS  4194304     /* NROWS*DIM */
#define LOSS_OFF  4194304
#define CODES_OFF 4194305

// 512 MB scratch: holds fp32 logits, then overwritten in-place with softmax weights.
static __device__ float  g_logits[(size_t)NROWS * NCODES];
static __device__ float  g_kl[NROWS];
static __device__ double g_part[4096];

// ---------------------------------------------------------------------------
// Threefry-2x32 (20 rounds), key = threefry_seed(42) = (0, 42)
// ---------------------------------------------------------------------------
__device__ __forceinline__ void threefry2x32(uint32_t x0, uint32_t x1,
                                             uint32_t& o0, uint32_t& o1) {
  const uint32_t ks0 = 0u;
  const uint32_t ks1 = 42u;
  const uint32_t ks2 = 0x1BD11BDAu ^ ks0 ^ ks1;
  x0 += ks0; x1 += ks1;
#define TF_R(r) { x0 += x1; x1 = __funnelshift_l(x1, x1, (r)); x1 ^= x0; }
  TF_R(13) TF_R(15) TF_R(26) TF_R(6)
  x0 += ks1; x1 += ks2 + 1u;
  TF_R(17) TF_R(29) TF_R(16) TF_R(24)
  x0 += ks2; x1 += ks0 + 2u;
  TF_R(13) TF_R(15) TF_R(26) TF_R(6)
  x0 += ks0; x1 += ks1 + 3u;
  TF_R(17) TF_R(29) TF_R(16) TF_R(24)
  x0 += ks1; x1 += ks2 + 4u;
  TF_R(13) TF_R(15) TF_R(26) TF_R(6)
  x0 += ks2; x1 += ks0 + 5u;
#undef TF_R
  o0 = x0; o1 = x1;
}

// jax_threefry_partitionable=True path (modern JAX default):
// per-element uint64 counter -> (hi=0, lo=idx); 32-bit draw = out0 ^ out1.
// uniform: f = bitcast(bits>>9 | 0x3f800000) - 1;  u = max(tiny, f*(1-tiny)+tiny)
// gumbel:  g = -log(-log(u))
__device__ __forceinline__ float gumbel_at(uint32_t idx) {
  uint32_t o0, o1;
  threefry2x32(0u, idx, o0, o1);
  uint32_t bits = o0 ^ o1;
  float f = __uint_as_float((bits >> 9) | 0x3f800000u) - 1.0f;
  float u = fmaxf(1.17549435e-38f, f + 1.17549435e-38f);
  return -logf(-logf(u));
}

// ---------------------------------------------------------------------------
// GEMM NT: C[m,n] = sum_k A[m*K+k] * B[n*K+k]   (logits = z @ codebook^T)
// 128x128 tile, BK=16, 256 threads, 8x8 per thread
// ---------------------------------------------------------------------------
__global__ __launch_bounds__(256, 2) void gemm_nt_kernel(
    const float* __restrict__ A, const float* __restrict__ B,
    float* __restrict__ C, int M, int N, int K)
{
  __shared__ float As[16][132];
  __shared__ float Bs[16][132];
  const int bm = blockIdx.y * 128;
  const int bn = blockIdx.x * 128;
  const int t  = threadIdx.x;
  const int tx = t & 15;
  const int ty = t >> 4;

  float acc[8][8];
#pragma unroll
  for (int i = 0; i < 8; ++i)
#pragma unroll
    for (int j = 0; j < 8; ++j) acc[i][j] = 0.0f;

  for (int k0 = 0; k0 < K; k0 += 16) {
#pragma unroll
    for (int i = 0; i < 2; ++i) {
      int idx = t + i * 256;
      int row = idx >> 2;
      int kq  = (idx & 3) << 2;
      float4 va = *(const float4*)(A + (size_t)(bm + row) * K + k0 + kq);
      As[kq + 0][row] = va.x;
      As[kq + 1][row] = va.y;
      As[kq + 2][row] = va.z;
      As[kq + 3][row] = va.w;
      float4 vb = *(const float4*)(B + (size_t)(bn + row) * K + k0 + kq);
      Bs[kq + 0][row] = vb.x;
      Bs[kq + 1][row] = vb.y;
      Bs[kq + 2][row] = vb.z;
      Bs[kq + 3][row] = vb.w;
    }
    __syncthreads();
#pragma unroll
    for (int kk = 0; kk < 16; ++kk) {
      float a[8], b[8];
      *(float4*)(a)     = *(const float4*)(&As[kk][ty * 8]);
      *(float4*)(a + 4) = *(const float4*)(&As[kk][ty * 8 + 4]);
      *(float4*)(b)     = *(const float4*)(&Bs[kk][tx * 8]);
      *(float4*)(b + 4) = *(const float4*)(&Bs[kk][tx * 8 + 4]);
#pragma unroll
      for (int i = 0; i < 8; ++i)
#pragma unroll
        for (int j = 0; j < 8; ++j)
          acc[i][j] = fmaf(a[i], b[j], acc[i][j]);
    }
    __syncthreads();
  }
#pragma unroll
  for (int i = 0; i < 8; ++i) {
    float* cp = C + (size_t)(bm + ty * 8 + i) * N + bn + tx * 8;
    *(float4*)(cp)     = make_float4(acc[i][0], acc[i][1], acc[i][2], acc[i][3]);
    *(float4*)(cp + 4) = make_float4(acc[i][4], acc[i][5], acc[i][6], acc[i][7]);
  }
}

// ---------------------------------------------------------------------------
// GEMM NN: C[m,n] = sum_k A[m*K+k] * B[k*N+n]   (z_q = W @ codebook)
// ---------------------------------------------------------------------------
__global__ __launch_bounds__(256, 2) void gemm_nn_kernel(
    const float* __restrict__ A, const float* __restrict__ B,
    float* __restrict__ C, int M, int N, int K)
{
  __shared__ float As[16][132];
  __shared__ float Bs[16][132];
  const int bm = blockIdx.y * 128;
  const int bn = blockIdx.x * 128;
  const int t  = threadIdx.x;
  const int tx = t & 15;
  const int ty = t >> 4;

  float acc[8][8];
#pragma unroll
  for (int i = 0; i < 8; ++i)
#pragma unroll
    for (int j = 0; j < 8; ++j) acc[i][j] = 0.0f;

  for (int k0 = 0; k0 < K; k0 += 16) {
#pragma unroll
    for (int i = 0; i < 2; ++i) {
      int idx = t + i * 256;
      int row = idx >> 2;
      int kq  = (idx & 3) << 2;
      float4 va = *(const float4*)(A + (size_t)(bm + row) * K + k0 + kq);
      As[kq + 0][row] = va.x;
      As[kq + 1][row] = va.y;
      As[kq + 2][row] = va.z;
      As[kq + 3][row] = va.w;
      int kr = idx >> 5;
      int nc = (idx & 31) << 2;
      *(float4*)(&Bs[kr][nc]) =
          *(const float4*)(B + (size_t)(k0 + kr) * N + bn + nc);
    }
    __syncthreads();
#pragma unroll
    for (int kk = 0; kk < 16; ++kk) {
      float a[8], b[8];
      *(float4*)(a)     = *(const float4*)(&As[kk][ty * 8]);
      *(float4*)(a + 4) = *(const float4*)(&As[kk][ty * 8 + 4]);
      *(float4*)(b)     = *(const float4*)(&Bs[kk][tx * 8]);
      *(float4*)(b + 4) = *(const float4*)(&Bs[kk][tx * 8 + 4]);
#pragma unroll
      for (int i = 0; i < 8; ++i)
#pragma unroll
        for (int j = 0; j < 8; ++j)
          acc[i][j] = fmaf(a[i], b[j], acc[i][j]);
    }
    __syncthreads();
  }
#pragma unroll
  for (int i = 0; i < 8; ++i) {
    float* cp = C + (size_t)(bm + ty * 8 + i) * N + bn + tx * 8;
    *(float4*)(cp)     = make_float4(acc[i][0], acc[i][1], acc[i][2], acc[i][3]);
    *(float4*)(cp + 4) = make_float4(acc[i][4], acc[i][5], acc[i][6], acc[i][7]);
  }
}

// ---------------------------------------------------------------------------
// Per-row: gumbel noise, two softmax stats, argmax, KL row-sum.
// Overwrites logits row with gumbel-softmax weights. One CTA per row.
// ---------------------------------------------------------------------------
__global__ __launch_bounds__(256) void row_kernel(float* __restrict__ logits,
                                                  float* __restrict__ out)
{
  __shared__ float redf[256];
  __shared__ float redg[256];
  __shared__ int   redi[256];

  const int row = blockIdx.x;
  const int t   = threadIdx.x;
  float* __restrict__ lrow = logits + (size_t)row * NCODES;
  const uint32_t base = (uint32_t)row * (uint32_t)NCODES;

  float lv[32], yv[32];
  float bestl = -CUDART_INF_F;
  int   besti = 0;
  float m2 = -CUDART_INF_F;

#pragma unroll
  for (int i = 0; i < 32; ++i) {
    int c = i * 256 + t;
    float l = lrow[c];
    float g = gumbel_at(base + (uint32_t)c);
    float y = l + g;                 // tau = 1.0
    lv[i] = l;
    yv[i] = y;
    if (l > bestl) { bestl = l; besti = c; }
    m2 = fmaxf(m2, y);
  }

  redf[t] = bestl; redi[t] = besti; redg[t] = m2;
  __syncthreads();
  for (int s = 128; s > 0; s >>= 1) {
    if (t < s) {
      float v = redf[t + s]; int vi = redi[t + s];
      if (v > redf[t] || (v == redf[t] && vi < redi[t])) { redf[t] = v; redi[t] = vi; }
      redg[t] = fmaxf(redg[t], redg[t + s]);
    }
    __syncthreads();
  }
  const float M1 = redf[0];
  const int   AM = redi[0];
  const float M2 = redg[0];
  __syncthreads();

  float z1 = 0.0f, z2 = 0.0f;
#pragma unroll
  for (int i = 0; i < 32; ++i) {
    z1 += expf(lv[i] - M1);
    z2 += expf(yv[i] - M2);
  }
  redf[t] = z1; redg[t] = z2;
  __syncthreads();
  for (int s = 128; s > 0; s >>= 1) {
    if (t < s) { redf[t] += redf[t + s]; redg[t] += redg[t + s]; }
    __syncthreads();
  }
  const float lZ1 = logf(redf[0]);
  const float rZ2 = 1.0f / redg[0];
  __syncthreads();

  float kl = 0.0f;
#pragma unroll
  for (int i = 0; i < 32; ++i) {
    int c = i * 256 + t;
    float sh = lv[i] - M1;
    float q  = expf(sh - lZ1);                       // qy = exp(log_softmax)
    kl += q * logf(q * 8192.0f + 1e-10f);
    lrow[c] = expf(yv[i] - M2) * rZ2;                // gumbel-softmax weight
  }
  redf[t] = kl;
  __syncthreads();
  for (int s = 128; s > 0; s >>= 1) {
    if (t < s) redf[t] += redf[t + s];
    __syncthreads();
  }
  if (t == 0) {
    g_kl[row] = redf[0];
    out[CODES_OFF + row] = (float)AM;
  }
}

// ---------------------------------------------------------------------------
// Straight-through + commit-loss partial sums. z_q already in out[0:ZQ_ELEMS].
// ---------------------------------------------------------------------------
__global__ __launch_bounds__(256) void st_commit_kernel(const float* __restrict__ z,
                                                        float* __restrict__ out)
{
  __shared__ double red[256];
  const int t = threadIdx.x;
  const size_t i4 = ((size_t)blockIdx.x * 256 + t) * 4;
  float4 zq = *(const float4*)(out + i4);
  float4 zv = *(const float4*)(z + i4);
  float dx = zq.x - zv.x;
  float dy = zq.y - zv.y;
  float dz = zq.z - zv.z;
  float dw = zq.w - zv.w;
  // z_q_st = z + (z_q - z), matching reference rounding
  *(float4*)(out + i4) = make_float4(zv.x + dx, zv.y + dy, zv.z + dz, zv.w + dw);
  red[t] = (double)(dx * dx) + (double)(dy * dy) +
           (double)(dz * dz) + (double)(dw * dw);
  __syncthreads();
  for (int s = 128; s > 0; s >>= 1) {
    if (t < s) red[t] += red[t + s];
    __syncthreads();
  }
  if (t == 0) g_part[blockIdx.x] = red[0];
}

__global__ __launch_bounds__(256) void finalize_kernel(float* __restrict__ out)
{
  __shared__ double red[256];
  const int t = threadIdx.x;

  double cs = 0.0;
  for (int i = t; i < 4096; i += 256) cs += g_part[i];
  red[t] = cs;
  __syncthreads();
  for (int s = 128; s > 0; s >>= 1) { if (t < s) red[t] += red[t + s]; __syncthreads(); }
  const double commit_sum = red[0];
  __syncthreads();

  double ks = 0.0;
  for (int i = t; i < NROWS; i += 256) ks += (double)g_kl[i];
  red[t] = ks;
  __syncthreads();
  for (int s = 128; s > 0; s >>= 1) { if (t < s) red[t] += red[t + s]; __syncthreads(); }

  if (t == 0) {
    float commit = 0.25f * (float)(commit_sum / (double)ZQ_ELEMS);
    float klm    = 0.01f * (float)(red[0] / (double)NROWS);
    out[LOSS_OFF] = commit + klm;
  }
}

// ---------------------------------------------------------------------------
extern "C" void kernel_launch(void* const* d_in, const int* in_sizes, int n_in,
                              void* d_out, int out_size)
{
  const float* z  = (const float*)d_in[0];
  const float* cb = (const float*)d_in[1];
  float* out = (float*)d_out;

  void* sym = nullptr;
  cudaGetSymbolAddress(&sym, g_logits);
  float* logits = (float*)sym;

  dim3 g1(NCODES / 128, NROWS / 128);           // 64 x 128
  gemm_nt_kernel<<<g1, 256>>>(z, cb, logits, NROWS, NCODES, DIM);

  row_kernel<<<NROWS, 256>>>(logits, out);

  dim3 g2(DIM / 128, NROWS / 128);              // 2 x 128
  gemm_nn_kernel<<<g2, 256>>>(logits, cb, out, NROWS, DIM, NCODES);

  st_commit_kernel<<<ZQ_ELEMS / 1024, 256>>>(z, out);
  finalize_kernel<<<1, 256>>>(out);
}

// round 8
// speedup vs baseline: 1.1922x; 1.1913x over previous
#include <cuda_runtime.h>
#include <cuda_bf16.h>
#include <cstdint>
#include <cstddef>
#include <math_constants.h>

#define NROWS     16384
#define NCODES    8192
#define DIM       256
#define ZQ_ELEMS  4194304
#define LOSS_OFF  4194304
#define CODES_OFF 4194305
#define GAP_THR   1e-3f

static __device__ float  g_logits[(size_t)NROWS * NCODES];                    // 512 MB
static __device__ __align__(16) __nv_bfloat16 g_wh[(size_t)NROWS * NCODES];   // 256 MB
static __device__ __align__(16) __nv_bfloat16 g_wl[(size_t)NROWS * NCODES];   // 256 MB
static __device__ __align__(16) __nv_bfloat16 g_zh[(size_t)NROWS * DIM];
static __device__ __align__(16) __nv_bfloat16 g_zl[(size_t)NROWS * DIM];
static __device__ __align__(16) __nv_bfloat16 g_ch[(size_t)NCODES * DIM];
static __device__ __align__(16) __nv_bfloat16 g_cl[(size_t)NCODES * DIM];
static __device__ __align__(16) __nv_bfloat16 g_cth[(size_t)DIM * NCODES];
static __device__ __align__(16) __nv_bfloat16 g_ctl[(size_t)DIM * NCODES];
static __device__ float  g_kl[NROWS];
static __device__ double g_part[256];
static __device__ int    g_fixn;
static __device__ int    g_fixrows[NROWS];

// ---------------- Threefry-2x32 (bit-exact JAX, key (0,42)) ----------------
// NOTE: full-precision logf is REQUIRED here. __logf has ~2^-21 ABSOLUTE error
// near 1, which corrupts exactly the largest gumbels (u ~ 1) by ~1e-3..1e-2,
// and those dominate the softmax -> 6e-3 z_q error (R6/R7 failures).
__device__ __forceinline__ float gumbel_at(uint32_t idx) {
  uint32_t x0 = 0u, x1 = idx;
  const uint32_t ks0 = 0u, ks1 = 42u, ks2 = 0x1BD11BDAu ^ ks0 ^ ks1;
  x0 += ks0; x1 += ks1;
#define TF_R(r) { x0 += x1; x1 = __funnelshift_l(x1, x1, (r)); x1 ^= x0; }
  TF_R(13) TF_R(15) TF_R(26) TF_R(6)  x0 += ks1; x1 += ks2 + 1u;
  TF_R(17) TF_R(29) TF_R(16) TF_R(24) x0 += ks2; x1 += ks0 + 2u;
  TF_R(13) TF_R(15) TF_R(26) TF_R(6)  x0 += ks0; x1 += ks1 + 3u;
  TF_R(17) TF_R(29) TF_R(16) TF_R(24) x0 += ks1; x1 += ks2 + 4u;
  TF_R(13) TF_R(15) TF_R(26) TF_R(6)  x0 += ks2; x1 += ks0 + 5u;
#undef TF_R
  uint32_t bits = x0 ^ x1;
  float f = __uint_as_float((bits >> 9) | 0x3f800000u) - 1.0f;
  float u = fmaxf(1.17549435e-38f, f + 1.17549435e-38f);
  return -logf(-logf(u));
}

// ---------------- conversions (fp32 -> bf16 hi/lo splits) -------------------
__global__ __launch_bounds__(256) void conv_z_kernel(const float* __restrict__ z) {
  size_t i = (size_t)blockIdx.x * 256 + threadIdx.x;
  float v = z[i];
  __nv_bfloat16 hi = __float2bfloat16(v);
  g_zh[i] = hi;
  g_zl[i] = __float2bfloat16(v - __bfloat162float(hi));
}
__global__ __launch_bounds__(256) void conv_cb_kernel(const float* __restrict__ cb) {
  size_t i = (size_t)blockIdx.x * 256 + threadIdx.x;
  float v = cb[i];
  __nv_bfloat16 hi = __float2bfloat16(v);
  __nv_bfloat16 lo = __float2bfloat16(v - __bfloat162float(hi));
  size_t row = i >> 8; int c = (int)(i & 255);
  g_ch[i] = hi;
  g_cl[i] = lo;
  g_cth[(size_t)c * NCODES + row] = hi;
  g_ctl[(size_t)c * NCODES + row] = lo;
  if (i == 0) g_fixn = 0;
}

// ---------------- HMMA bf16 NT GEMM, 3-phase split, 128x128x32 --------------
#define APITCH 80          /* bytes per 32-col bf16 row in smem (conflict-free) */
#define STAGE_BYTES 20480  /* A(10240) + B(10240) */
#define GEMM_SMEM (4 * STAGE_BYTES)   /* 81920; epilogue reuses it */

__device__ __forceinline__ uint32_t smem_u32(const void* p) {
  uint32_t a;
  asm("{ .reg .u64 t; cvta.to.shared.u64 t, %1; cvt.u32.u64 %0, t; }" : "=r"(a) : "l"(p));
  return a;
}
__device__ __forceinline__ void ldsm4(uint32_t a, uint32_t& r0, uint32_t& r1,
                                      uint32_t& r2, uint32_t& r3) {
  asm volatile("ldmatrix.sync.aligned.m8n8.x4.shared.b16 {%0,%1,%2,%3}, [%4];"
               : "=r"(r0), "=r"(r1), "=r"(r2), "=r"(r3) : "r"(a));
}
__device__ __forceinline__ void mma16816(float* d, const uint32_t* a,
                                         uint32_t b0, uint32_t b1) {
  asm volatile("mma.sync.aligned.m16n8k16.row.col.f32.bf16.bf16.f32 "
               "{%0,%1,%2,%3}, {%4,%5,%6,%7}, {%8,%9}, {%0,%1,%2,%3};"
               : "+f"(d[0]), "+f"(d[1]), "+f"(d[2]), "+f"(d[3])
               : "r"(a[0]), "r"(a[1]), "r"(a[2]), "r"(a[3]), "r"(b0), "r"(b1));
}

__device__ __forceinline__ void load_stage(uint32_t sbase,
    const __nv_bfloat16* __restrict__ A, const __nv_bfloat16* __restrict__ B,
    size_t bm, size_t bn, int k0, int K, int t)
{
#pragma unroll
  for (int j = 0; j < 2; ++j) {
    int idx = t + j * 256;            // 0..511
    int r = idx >> 2, c = idx & 3;
    uint32_t da = sbase + (uint32_t)(r * APITCH + c * 16);
    const void* sa = A + (bm + (size_t)r) * (size_t)K + k0 + c * 8;
    asm volatile("cp.async.cg.shared.global [%0], [%1], 16;" :: "r"(da), "l"(sa));
    uint32_t db = sbase + 10240 + (uint32_t)(r * APITCH + c * 16);
    const void* sb = B + (bn + (size_t)r) * (size_t)K + k0 + c * 8;
    asm volatile("cp.async.cg.shared.global [%0], [%1], 16;" :: "r"(db), "l"(sb));
  }
  asm volatile("cp.async.commit_group;");
}

__device__ __forceinline__ void load_gk(int g, int KTp, int Kp, uint32_t sb0,
    const __nv_bfloat16* A0, const __nv_bfloat16* A1, const __nv_bfloat16* A2,
    const __nv_bfloat16* B0, const __nv_bfloat16* B1, const __nv_bfloat16* B2,
    size_t bm, size_t bn, int t)
{
  int ph = g / KTp;
  int k0 = (g - ph * KTp) << 5;
  const __nv_bfloat16* Ap = (ph == 0) ? A0 : ((ph == 1) ? A1 : A2);
  const __nv_bfloat16* Bp = (ph == 0) ? B0 : ((ph == 1) ? B1 : B2);
  load_stage(sb0 + (uint32_t)((g & 3) * STAGE_BYTES), Ap, Bp, bm, bn, k0, Kp, t);
}

__global__ __launch_bounds__(256, 2) void gemm3_hmma_kernel(
    const __nv_bfloat16* __restrict__ A0, const __nv_bfloat16* __restrict__ A1,
    const __nv_bfloat16* __restrict__ A2,
    const __nv_bfloat16* __restrict__ B0, const __nv_bfloat16* __restrict__ B1,
    const __nv_bfloat16* __restrict__ B2,
    float* __restrict__ C, int Ntot, int Kp,
    const float* __restrict__ Zres, double* __restrict__ part)
{
  extern __shared__ char smem[];
  const uint32_t sb0 = smem_u32(smem);
  const int t = threadIdx.x;
  const int wid = t >> 5, lane = t & 31;
  const int wm = wid >> 1, wn = wid & 1;     // 4 x 2 warp grid, warp tile 32x64
  const size_t bm = (size_t)blockIdx.y * 128;
  const size_t bn = (size_t)blockIdx.x * 128;
  const int KTp = Kp >> 5;
  const int KTtot = KTp * 3;

  float acc[2][8][4];
#pragma unroll
  for (int mi = 0; mi < 2; ++mi)
#pragma unroll
    for (int ni = 0; ni < 8; ++ni)
#pragma unroll
      for (int q = 0; q < 4; ++q) acc[mi][ni][q] = 0.0f;

  load_gk(0, KTp, Kp, sb0, A0, A1, A2, B0, B1, B2, bm, bn, t);
  load_gk(1, KTp, Kp, sb0, A0, A1, A2, B0, B1, B2, bm, bn, t);
  load_gk(2, KTp, Kp, sb0, A0, A1, A2, B0, B1, B2, bm, bn, t);

  const uint32_t aoff = (uint32_t)((wm * 32 + (lane & 15)) * APITCH + (lane >> 4) * 16);
  const uint32_t boff = 10240u + (uint32_t)((wn * 64 + (lane & 15)) * APITCH + (lane >> 4) * 16);

  for (int k = 0; k < KTtot; ++k) {
    asm volatile("cp.async.wait_group 2;");
    __syncthreads();
    if (k + 3 < KTtot)
      load_gk(k + 3, KTp, Kp, sb0, A0, A1, A2, B0, B1, B2, bm, bn, t);
    else
      asm volatile("cp.async.commit_group;");

    const uint32_t sbase = sb0 + (uint32_t)((k & 3) * STAGE_BYTES);
#pragma unroll
    for (int kk = 0; kk < 2; ++kk) {
      uint32_t a0[4], a1[4];
      ldsm4(sbase + aoff + kk * 32,               a0[0], a0[1], a0[2], a0[3]);
      ldsm4(sbase + aoff + 16 * APITCH + kk * 32, a1[0], a1[1], a1[2], a1[3]);
      uint32_t bfr[8][2];
#pragma unroll
      for (int nj = 0; nj < 4; ++nj) {
        uint32_t r0, r1, r2, r3;
        ldsm4(sbase + boff + nj * 16 * APITCH + kk * 32, r0, r1, r2, r3);
        bfr[2 * nj + 0][0] = r0; bfr[2 * nj + 0][1] = r2;
        bfr[2 * nj + 1][0] = r1; bfr[2 * nj + 1][1] = r3;
      }
#pragma unroll
      for (int ni = 0; ni < 8; ++ni) {
        mma16816(acc[0][ni], a0, bfr[ni][0], bfr[ni][1]);
        mma16816(acc[1][ni], a1, bfr[ni][0], bfr[ni][1]);
      }
    }
    __syncthreads();
  }
  asm volatile("cp.async.wait_group 0;");
  __syncthreads();

  // fp32 epilogue: stage to smem [128][132], coalesced global
  const int r4 = lane >> 2;
  const int c4 = (lane & 3) * 2;
  float* sC = (float*)smem;
#pragma unroll
  for (int mi = 0; mi < 2; ++mi)
#pragma unroll
    for (int ni = 0; ni < 8; ++ni) {
      int row = wm * 32 + mi * 16 + r4;
      int col = wn * 64 + ni * 8 + c4;
      sC[(size_t)row * 132 + col]     = acc[mi][ni][0];
      sC[(size_t)row * 132 + col + 1] = acc[mi][ni][1];
      sC[(size_t)(row + 8) * 132 + col]     = acc[mi][ni][2];
      sC[(size_t)(row + 8) * 132 + col + 1] = acc[mi][ni][3];
    }
  __syncthreads();

  if (Zres == nullptr) {
#pragma unroll
    for (int j = 0; j < 16; ++j) {
      int idx = t + j * 256;
      int r = idx >> 5, ch = idx & 31;
      float4 v = ((const float4*)sC)[r * 33 + ch];
      *(float4*)(C + (bm + (size_t)r) * (size_t)Ntot + bn + ch * 4) = v;
    }
  } else {
    double dsum = 0.0;
#pragma unroll
    for (int j = 0; j < 16; ++j) {
      int idx = t + j * 256;
      int r = idx >> 5, ch = idx & 31;
      float4 v = ((const float4*)sC)[r * 33 + ch];
      size_t go = (bm + (size_t)r) * (size_t)Ntot + bn + ch * 4;
      float4 zv = *(const float4*)(Zres + go);
      float d0 = v.x - zv.x, d1 = v.y - zv.y, d2 = v.z - zv.z, d3 = v.w - zv.w;
      *(float4*)(C + go) = make_float4(zv.x + d0, zv.y + d1, zv.z + d2, zv.w + d3);
      dsum += (double)(d0 * d0) + (double)(d1 * d1) +
              (double)(d2 * d2) + (double)(d3 * d3);
    }
    __syncthreads();
    double* red = (double*)smem;
    red[t] = dsum;
    __syncthreads();
    for (int s = 128; s > 0; s >>= 1) {
      if (t < s) red[t] += red[t + s];
      __syncthreads();
    }
    if (t == 0) part[blockIdx.y * gridDim.x + blockIdx.x] = red[0];
  }
}

// ---------------- per-row: gumbel, softmaxes, argmax+gap, KL, w hi/lo -------
__global__ __launch_bounds__(256) void row_kernel(float* __restrict__ out)
{
  __shared__ float redf[256], reds[256], redg[256];
  __shared__ int   redi[256];
  const int row = blockIdx.x, t = threadIdx.x;
  const float* __restrict__ lrow = g_logits + (size_t)row * NCODES + t * 32;
  const uint32_t base = (uint32_t)row * (uint32_t)NCODES + (uint32_t)(t * 32);

  float lv[32], yv[32];
#pragma unroll
  for (int j = 0; j < 8; ++j) *(float4*)(lv + j * 4) = ((const float4*)lrow)[j];

  float m1 = -CUDART_INF_F, m2nd = -CUDART_INF_F, my = -CUDART_INF_F;
  int i1 = 0;
#pragma unroll
  for (int i = 0; i < 32; ++i) {
    float l = lv[i];
    float y = l + gumbel_at(base + (uint32_t)i);
    yv[i] = y;
    if (l > m1) { m2nd = m1; m1 = l; i1 = t * 32 + i; }
    else if (l > m2nd) m2nd = l;
    my = fmaxf(my, y);
  }
  redf[t] = m1; redi[t] = i1; reds[t] = m2nd; redg[t] = my;
  __syncthreads();
  for (int s = 128; s > 0; s >>= 1) {
    if (t < s) {
      float a1 = redf[t], a2 = reds[t]; int ai = redi[t];
      float b1 = redf[t + s], b2 = reds[t + s]; int bi = redi[t + s];
      float n1, n2; int ni;
      if (b1 > a1)      { n1 = b1; ni = bi; n2 = fmaxf(a1, b2); }
      else if (b1 < a1) { n1 = a1; ni = ai; n2 = fmaxf(b1, a2); }
      else              { n1 = a1; ni = (ai < bi) ? ai : bi; n2 = a1; }
      redf[t] = n1; redi[t] = ni; reds[t] = n2;
      redg[t] = fmaxf(redg[t], redg[t + s]);
    }
    __syncthreads();
  }
  const float M1 = redf[0]; const int AM = redi[0];
  const float GAP = M1 - reds[0]; const float M2 = redg[0];
  __syncthreads();

  float z1 = 0.0f, z2 = 0.0f;
#pragma unroll
  for (int i = 0; i < 32; ++i) { z1 += __expf(lv[i] - M1); z2 += __expf(yv[i] - M2); }
  redf[t] = z1; redg[t] = z2;
  __syncthreads();
  for (int s = 128; s > 0; s >>= 1) {
    if (t < s) { redf[t] += redf[t + s]; redg[t] += redg[t + s]; }
    __syncthreads();
  }
  const float lZ1 = logf(redf[0]); const float rZ2 = 1.0f / redg[0];
  __syncthreads();

  float kl = 0.0f;
  __nv_bfloat16 whl[32], wll[32];
#pragma unroll
  for (int i = 0; i < 32; ++i) {
    float q = __expf(lv[i] - M1 - lZ1);
    kl += q * __logf(q * 8192.0f + 1e-10f);
    float w = __expf(yv[i] - M2) * rZ2;
    __nv_bfloat16 hi = __float2bfloat16(w);
    whl[i] = hi;
    wll[i] = __float2bfloat16(w - __bfloat162float(hi));
  }
  {
    __nv_bfloat16* wh = g_wh + (size_t)row * NCODES + t * 32;
    __nv_bfloat16* wl = g_wl + (size_t)row * NCODES + t * 32;
#pragma unroll
    for (int j = 0; j < 4; ++j) {
      ((uint4*)wh)[j] = ((const uint4*)whl)[j];
      ((uint4*)wl)[j] = ((const uint4*)wll)[j];
    }
  }
  redf[t] = kl;
  __syncthreads();
  for (int s = 128; s > 0; s >>= 1) { if (t < s) redf[t] += redf[t + s]; __syncthreads(); }
  if (t == 0) {
    g_kl[row] = redf[0];
    out[CODES_OFF + row] = (float)AM;
    if (GAP < GAP_THR) g_fixrows[atomicAdd(&g_fixn, 1)] = row;
  }
}

// ---------------- exact fp32 rescore for near-tie rows ----------------------
__global__ __launch_bounds__(256) void fixup_kernel(const float* __restrict__ z,
                                                    const float* __restrict__ cb,
                                                    float* __restrict__ out)
{
  __shared__ float zs[256]; __shared__ float rv[256]; __shared__ int ri[256];
  const int t = threadIdx.x;
  const int nfix = g_fixn;
  for (int e = blockIdx.x; e < nfix; e += gridDim.x) {
    const int row = g_fixrows[e];
    zs[t] = z[(size_t)row * DIM + t];
    __syncthreads();
    float best = -CUDART_INF_F; int bi = 0;
    for (int c = t; c < NCODES; c += 256) {
      const float* cp = cb + (size_t)c * DIM;
      float s = 0.0f;
#pragma unroll 8
      for (int k = 0; k < DIM; ++k) s = fmaf(zs[k], cp[k], s);
      if (s > best) { best = s; bi = c; }
    }
    rv[t] = best; ri[t] = bi;
    __syncthreads();
    for (int s = 128; s > 0; s >>= 1) {
      if (t < s) {
        float v = rv[t + s]; int vi = ri[t + s];
        if (v > rv[t] || (v == rv[t] && vi < ri[t])) { rv[t] = v; ri[t] = vi; }
      }
      __syncthreads();
    }
    if (t == 0) out[CODES_OFF + row] = (float)ri[0];
    __syncthreads();
  }
}

// ---------------- finalize losses ------------------------------------------
__global__ __launch_bounds__(256) void finalize_kernel(float* __restrict__ out)
{
  __shared__ double red[256];
  const int t = threadIdx.x;
  red[t] = g_part[t];
  __syncthreads();
  for (int s = 128; s > 0; s >>= 1) { if (t < s) red[t] += red[t + s]; __syncthreads(); }
  const double commit_sum = red[0];
  __syncthreads();
  double ks = 0.0;
  for (int i = t; i < NROWS; i += 256) ks += (double)g_kl[i];
  red[t] = ks;
  __syncthreads();
  for (int s = 128; s > 0; s >>= 1) { if (t < s) red[t] += red[t + s]; __syncthreads(); }
  if (t == 0) {
    float commit = 0.25f * (float)(commit_sum / (double)ZQ_ELEMS);
    float klm    = 0.01f * (float)(red[0] / (double)NROWS);
    out[LOSS_OFF] = commit + klm;
  }
}

// ---------------- launch ----------------------------------------------------
extern "C" void kernel_launch(void* const* d_in, const int* in_sizes, int n_in,
                              void* d_out, int out_size)
{
  const float* z  = (const float*)d_in[0];
  const float* cb = (const float*)d_in[1];
  float* out = (float*)d_out;

  void *pl, *pwh, *pwl, *pzh, *pzl, *pch, *pcl, *pcth, *pctl, *ppart;
  cudaGetSymbolAddress(&pl, g_logits);
  cudaGetSymbolAddress(&pwh, g_wh);
  cudaGetSymbolAddress(&pwl, g_wl);
  cudaGetSymbolAddress(&pzh, g_zh);
  cudaGetSymbolAddress(&pzl, g_zl);
  cudaGetSymbolAddress(&pch, g_ch);
  cudaGetSymbolAddress(&pcl, g_cl);
  cudaGetSymbolAddress(&pcth, g_cth);
  cudaGetSymbolAddress(&pctl, g_ctl);
  cudaGetSymbolAddress(&ppart, g_part);

  cudaFuncSetAttribute(gemm3_hmma_kernel,
                       cudaFuncAttributeMaxDynamicSharedMemorySize, GEMM_SMEM);

  conv_z_kernel<<<ZQ_ELEMS / 256, 256>>>(z);
  conv_cb_kernel<<<(NCODES * DIM) / 256, 256>>>(cb);

  // GEMM1: logits(fp32) = zh*ch + zh*cl + zl*ch   [16384 x 8192], Kp=256
  dim3 g1(NCODES / 128, NROWS / 128);
  gemm3_hmma_kernel<<<g1, 256, GEMM_SMEM>>>(
      (const __nv_bfloat16*)pzh, (const __nv_bfloat16*)pzh, (const __nv_bfloat16*)pzl,
      (const __nv_bfloat16*)pch, (const __nv_bfloat16*)pcl, (const __nv_bfloat16*)pch,
      (float*)pl, NCODES, DIM, nullptr, nullptr);

  row_kernel<<<NROWS, 256>>>(out);

  // GEMM2: z_q = wh*cth + wh*ctl + wl*cth   [16384 x 256], Kp=8192, fused ST+commit
  dim3 g2(DIM / 128, NROWS / 128);
  gemm3_hmma_kernel<<<g2, 256, GEMM_SMEM>>>(
      (const __nv_bfloat16*)pwh, (const __nv_bfloat16*)pwh, (const __nv_bfloat16*)pwl,
      (const __nv_bfloat16*)pcth, (const __nv_bfloat16*)pctl, (const __nv_bfloat16*)pcth,
      out, DIM, NCODES, z, (double*)ppart);

  fixup_kernel<<<128, 256>>>(z, cb, out);
  finalize_kernel<<<1, 256>>>(out);
}

// round 9
// speedup vs baseline: 1.3408x; 1.1247x over previous
#include <cuda_runtime.h>
#include <cuda_bf16.h>
#include <cuda_fp16.h>
#include <cstdint>
#include <cstddef>
#include <math_constants.h>

#define NROWS     16384
#define NCODES    8192
#define DIM       256
#define ZQ_ELEMS  4194304
#define LOSS_OFF  4194304
#define CODES_OFF 4194305
#define GAP_THR   1e-3f

static __device__ float  g_logits[(size_t)NROWS * NCODES];                    // 512 MB
static __device__ __align__(16) __half        g_w16[(size_t)NROWS * NCODES];  // 256 MB
static __device__ __align__(16) __nv_bfloat16 g_zh[(size_t)NROWS * DIM];
static __device__ __align__(16) __nv_bfloat16 g_zl[(size_t)NROWS * DIM];
static __device__ __align__(16) __nv_bfloat16 g_ch[(size_t)NCODES * DIM];
static __device__ __align__(16) __nv_bfloat16 g_cl[(size_t)NCODES * DIM];
static __device__ __align__(16) __half        g_cth[(size_t)DIM * NCODES];    // fp16 T hi
static __device__ __align__(16) __half        g_ctl[(size_t)DIM * NCODES];    // fp16 T residual
static __device__ float  g_kl[NROWS];
static __device__ double g_part[256];
static __device__ int    g_fixn;
static __device__ int    g_fixrows[NROWS];

// ---------------- Threefry-2x32 (bit-exact JAX, key (0,42)) ----------------
// Inner log MUST be full-precision logf: __logf's ~2^-21 ABSOLUTE error makes
// e = -ln(u) carry huge RELATIVE error when u ~ 1, corrupting the largest
// gumbels (R6/R7 failures). The OUTER log is safe as __logf: its absolute
// error in g is <= max(2^-21, 2ulp * |ln e|) <= 2e-5.
__device__ __forceinline__ float gumbel_at(uint32_t idx) {
  uint32_t x0 = 0u, x1 = idx;
  const uint32_t ks0 = 0u, ks1 = 42u, ks2 = 0x1BD11BDAu ^ ks0 ^ ks1;
  x0 += ks0; x1 += ks1;
#define TF_R(r) { x0 += x1; x1 = __funnelshift_l(x1, x1, (r)); x1 ^= x0; }
  TF_R(13) TF_R(15) TF_R(26) TF_R(6)  x0 += ks1; x1 += ks2 + 1u;
  TF_R(17) TF_R(29) TF_R(16) TF_R(24) x0 += ks2; x1 += ks0 + 2u;
  TF_R(13) TF_R(15) TF_R(26) TF_R(6)  x0 += ks0; x1 += ks1 + 3u;
  TF_R(17) TF_R(29) TF_R(16) TF_R(24) x0 += ks1; x1 += ks2 + 4u;
  TF_R(13) TF_R(15) TF_R(26) TF_R(6)  x0 += ks2; x1 += ks0 + 5u;
#undef TF_R
  uint32_t bits = x0 ^ x1;
  float f = __uint_as_float((bits >> 9) | 0x3f800000u) - 1.0f;
  float u = fmaxf(1.17549435e-38f, f + 1.17549435e-38f);
  return -__logf(-logf(u));
}

// ---------------- conversions ----------------
__global__ __launch_bounds__(256) void conv_z_kernel(const float* __restrict__ z) {
  size_t i = (size_t)blockIdx.x * 256 + threadIdx.x;
  float v = z[i];
  __nv_bfloat16 hi = __float2bfloat16(v);
  g_zh[i] = hi;
  g_zl[i] = __float2bfloat16(v - __bfloat162float(hi));
}
__global__ __launch_bounds__(256) void conv_cb_kernel(const float* __restrict__ cb) {
  size_t i = (size_t)blockIdx.x * 256 + threadIdx.x;
  float v = cb[i];
  __nv_bfloat16 hi = __float2bfloat16(v);
  g_ch[i] = hi;
  g_cl[i] = __float2bfloat16(v - __bfloat162float(hi));
  size_t row = i >> 8; int c = (int)(i & 255);
  __half h16 = __float2half_rn(v);
  g_cth[(size_t)c * NCODES + row] = h16;
  g_ctl[(size_t)c * NCODES + row] = __float2half_rn(v - __half2float(h16));
}
__global__ void init_kernel() { g_fixn = 0; }

// ---------------- HMMA NT GEMM, NPH phases, 128x128x32, bf16 or fp16 --------
#define APITCH 80          /* bytes per 32-col 16b row in smem (conflict-free) */
#define STAGE_BYTES 20480  /* A(10240) + B(10240) */
#define GEMM_SMEM (4 * STAGE_BYTES)   /* 81920; epilogue reuses it */

__device__ __forceinline__ uint32_t smem_u32(const void* p) {
  uint32_t a;
  asm("{ .reg .u64 t; cvta.to.shared.u64 t, %1; cvt.u32.u64 %0, t; }" : "=r"(a) : "l"(p));
  return a;
}
__device__ __forceinline__ void ldsm4(uint32_t a, uint32_t& r0, uint32_t& r1,
                                      uint32_t& r2, uint32_t& r3) {
  asm volatile("ldmatrix.sync.aligned.m8n8.x4.shared.b16 {%0,%1,%2,%3}, [%4];"
               : "=r"(r0), "=r"(r1), "=r"(r2), "=r"(r3) : "r"(a));
}
template<int F16>
__device__ __forceinline__ void mma16816(float* d, const uint32_t* a,
                                         uint32_t b0, uint32_t b1) {
  if (F16)
    asm volatile("mma.sync.aligned.m16n8k16.row.col.f32.f16.f16.f32 "
                 "{%0,%1,%2,%3}, {%4,%5,%6,%7}, {%8,%9}, {%0,%1,%2,%3};"
                 : "+f"(d[0]), "+f"(d[1]), "+f"(d[2]), "+f"(d[3])
                 : "r"(a[0]), "r"(a[1]), "r"(a[2]), "r"(a[3]), "r"(b0), "r"(b1));
  else
    asm volatile("mma.sync.aligned.m16n8k16.row.col.f32.bf16.bf16.f32 "
                 "{%0,%1,%2,%3}, {%4,%5,%6,%7}, {%8,%9}, {%0,%1,%2,%3};"
                 : "+f"(d[0]), "+f"(d[1]), "+f"(d[2]), "+f"(d[3])
                 : "r"(a[0]), "r"(a[1]), "r"(a[2]), "r"(a[3]), "r"(b0), "r"(b1));
}

__device__ __forceinline__ void load_stage(uint32_t sbase,
    const uint16_t* __restrict__ A, const uint16_t* __restrict__ B,
    size_t bm, size_t bn, int k0, int K, int t)
{
#pragma unroll
  for (int j = 0; j < 2; ++j) {
    int idx = t + j * 256;            // 0..511
    int r = idx >> 2, c = idx & 3;
    uint32_t da = sbase + (uint32_t)(r * APITCH + c * 16);
    const void* sa = A + (bm + (size_t)r) * (size_t)K + k0 + c * 8;
    asm volatile("cp.async.cg.shared.global [%0], [%1], 16;" :: "r"(da), "l"(sa));
    uint32_t db = sbase + 10240 + (uint32_t)(r * APITCH + c * 16);
    const void* sb = B + (bn + (size_t)r) * (size_t)K + k0 + c * 8;
    asm volatile("cp.async.cg.shared.global [%0], [%1], 16;" :: "r"(db), "l"(sb));
  }
  asm volatile("cp.async.commit_group;");
}

__device__ __forceinline__ void load_gk(int g, int KTp, int Kp, uint32_t sb0,
    const uint16_t* A0, const uint16_t* A1, const uint16_t* A2,
    const uint16_t* B0, const uint16_t* B1, const uint16_t* B2,
    size_t bm, size_t bn, int t)
{
  int ph = g / KTp;
  int k0 = (g - ph * KTp) << 5;
  const uint16_t* Ap = (ph == 0) ? A0 : ((ph == 1) ? A1 : A2);
  const uint16_t* Bp = (ph == 0) ? B0 : ((ph == 1) ? B1 : B2);
  load_stage(sb0 + (uint32_t)((g & 3) * STAGE_BYTES), Ap, Bp, bm, bn, k0, Kp, t);
}

template<int NPH, int F16>
__global__ __launch_bounds__(256, 2) void gemm_hmma_kernel(
    const uint16_t* __restrict__ A0, const uint16_t* __restrict__ A1,
    const uint16_t* __restrict__ A2,
    const uint16_t* __restrict__ B0, const uint16_t* __restrict__ B1,
    const uint16_t* __restrict__ B2,
    float* __restrict__ C, int Ntot, int Kp,
    const float* __restrict__ Zres, double* __restrict__ part)
{
  extern __shared__ char smem[];
  const uint32_t sb0 = smem_u32(smem);
  const int t = threadIdx.x;
  const int wid = t >> 5, lane = t & 31;
  const int wm = wid >> 1, wn = wid & 1;     // 4 x 2 warp grid, warp tile 32x64
  const size_t bm = (size_t)blockIdx.y * 128;
  const size_t bn = (size_t)blockIdx.x * 128;
  const int KTp = Kp >> 5;
  const int KTtot = KTp * NPH;

  float acc[2][8][4];
#pragma unroll
  for (int mi = 0; mi < 2; ++mi)
#pragma unroll
    for (int ni = 0; ni < 8; ++ni)
#pragma unroll
      for (int q = 0; q < 4; ++q) acc[mi][ni][q] = 0.0f;

  load_gk(0, KTp, Kp, sb0, A0, A1, A2, B0, B1, B2, bm, bn, t);
  load_gk(1, KTp, Kp, sb0, A0, A1, A2, B0, B1, B2, bm, bn, t);
  load_gk(2, KTp, Kp, sb0, A0, A1, A2, B0, B1, B2, bm, bn, t);

  const uint32_t aoff = (uint32_t)((wm * 32 + (lane & 15)) * APITCH + (lane >> 4) * 16);
  const uint32_t boff = 10240u + (uint32_t)((wn * 64 + (lane & 15)) * APITCH + (lane >> 4) * 16);

  for (int k = 0; k < KTtot; ++k) {
    asm volatile("cp.async.wait_group 2;");
    __syncthreads();
    if (k + 3 < KTtot)
      load_gk(k + 3, KTp, Kp, sb0, A0, A1, A2, B0, B1, B2, bm, bn, t);
    else
      asm volatile("cp.async.commit_group;");

    const uint32_t sbase = sb0 + (uint32_t)((k & 3) * STAGE_BYTES);
#pragma unroll
    for (int kk = 0; kk < 2; ++kk) {
      uint32_t a0[4], a1[4];
      ldsm4(sbase + aoff + kk * 32,               a0[0], a0[1], a0[2], a0[3]);
      ldsm4(sbase + aoff + 16 * APITCH + kk * 32, a1[0], a1[1], a1[2], a1[3]);
      uint32_t bfr[8][2];
#pragma unroll
      for (int nj = 0; nj < 4; ++nj) {
        uint32_t r0, r1, r2, r3;
        ldsm4(sbase + boff + nj * 16 * APITCH + kk * 32, r0, r1, r2, r3);
        bfr[2 * nj + 0][0] = r0; bfr[2 * nj + 0][1] = r2;
        bfr[2 * nj + 1][0] = r1; bfr[2 * nj + 1][1] = r3;
      }
#pragma unroll
      for (int ni = 0; ni < 8; ++ni) {
        mma16816<F16>(acc[0][ni], a0, bfr[ni][0], bfr[ni][1]);
        mma16816<F16>(acc[1][ni], a1, bfr[ni][0], bfr[ni][1]);
      }
    }
    __syncthreads();
  }
  asm volatile("cp.async.wait_group 0;");
  __syncthreads();

  // fp32 epilogue: stage to smem [128][132], coalesced global
  const int r4 = lane >> 2;
  const int c4 = (lane & 3) * 2;
  float* sC = (float*)smem;
#pragma unroll
  for (int mi = 0; mi < 2; ++mi)
#pragma unroll
    for (int ni = 0; ni < 8; ++ni) {
      int row = wm * 32 + mi * 16 + r4;
      int col = wn * 64 + ni * 8 + c4;
      sC[(size_t)row * 132 + col]     = acc[mi][ni][0];
      sC[(size_t)row * 132 + col + 1] = acc[mi][ni][1];
      sC[(size_t)(row + 8) * 132 + col]     = acc[mi][ni][2];
      sC[(size_t)(row + 8) * 132 + col + 1] = acc[mi][ni][3];
    }
  __syncthreads();

  if (Zres == nullptr) {
#pragma unroll
    for (int j = 0; j < 16; ++j) {
      int idx = t + j * 256;
      int r = idx >> 5, ch = idx & 31;
      float4 v = ((const float4*)sC)[r * 33 + ch];
      *(float4*)(C + (bm + (size_t)r) * (size_t)Ntot + bn + ch * 4) = v;
    }
  } else {
    double dsum = 0.0;
#pragma unroll
    for (int j = 0; j < 16; ++j) {
      int idx = t + j * 256;
      int r = idx >> 5, ch = idx & 31;
      float4 v = ((const float4*)sC)[r * 33 + ch];
      size_t go = (bm + (size_t)r) * (size_t)Ntot + bn + ch * 4;
      float4 zv = *(const float4*)(Zres + go);
      float d0 = v.x - zv.x, d1 = v.y - zv.y, d2 = v.z - zv.z, d3 = v.w - zv.w;
      *(float4*)(C + go) = make_float4(zv.x + d0, zv.y + d1, zv.z + d2, zv.w + d3);
      dsum += (double)(d0 * d0) + (double)(d1 * d1) +
              (double)(d2 * d2) + (double)(d3 * d3);
    }
    __syncthreads();
    double* red = (double*)smem;
    red[t] = dsum;
    __syncthreads();
    for (int s = 128; s > 0; s >>= 1) {
      if (t < s) red[t] += red[t + s];
      __syncthreads();
    }
    if (t == 0) part[blockIdx.y * gridDim.x + blockIdx.x] = red[0];
  }
}

// ---------------- per-row: gumbel, softmaxes, argmax+gap, KL, w fp16 --------
__global__ __launch_bounds__(256) void row_kernel(float* __restrict__ out)
{
  __shared__ float redf[256], reds[256], redg[256];
  __shared__ int   redi[256];
  const int row = blockIdx.x, t = threadIdx.x;
  const float* __restrict__ lrow = g_logits + (size_t)row * NCODES + t * 32;
  const uint32_t base = (uint32_t)row * (uint32_t)NCODES + (uint32_t)(t * 32);

  float lv[32], yv[32];
#pragma unroll
  for (int j = 0; j < 8; ++j) *(float4*)(lv + j * 4) = ((const float4*)lrow)[j];

  float m1 = -CUDART_INF_F, m2nd = -CUDART_INF_F, my = -CUDART_INF_F;
  int i1 = 0;
#pragma unroll
  for (int i = 0; i < 32; ++i) {
    float l = lv[i];
    float y = l + gumbel_at(base + (uint32_t)i);
    yv[i] = y;
    if (l > m1) { m2nd = m1; m1 = l; i1 = t * 32 + i; }
    else if (l > m2nd) m2nd = l;
    my = fmaxf(my, y);
  }
  redf[t] = m1; redi[t] = i1; reds[t] = m2nd; redg[t] = my;
  __syncthreads();
  for (int s = 128; s > 0; s >>= 1) {
    if (t < s) {
      float a1 = redf[t], a2 = reds[t]; int ai = redi[t];
      float b1 = redf[t + s], b2 = reds[t + s]; int bi = redi[t + s];
      float n1, n2; int ni;
      if (b1 > a1)      { n1 = b1; ni = bi; n2 = fmaxf(a1, b2); }
      else if (b1 < a1) { n1 = a1; ni = ai; n2 = fmaxf(b1, a2); }
      else              { n1 = a1; ni = (ai < bi) ? ai : bi; n2 = a1; }
      redf[t] = n1; redi[t] = ni; reds[t] = n2;
      redg[t] = fmaxf(redg[t], redg[t + s]);
    }
    __syncthreads();
  }
  const float M1 = redf[0]; const int AM = redi[0];
  const float GAP = M1 - reds[0]; const float M2 = redg[0];
  __syncthreads();

  float z1 = 0.0f, z2 = 0.0f;
#pragma unroll
  for (int i = 0; i < 32; ++i) { z1 += __expf(lv[i] - M1); z2 += __expf(yv[i] - M2); }
  redf[t] = z1; redg[t] = z2;
  __syncthreads();
  for (int s = 128; s > 0; s >>= 1) {
    if (t < s) { redf[t] += redf[t + s]; redg[t] += redg[t + s]; }
    __syncthreads();
  }
  const float lZ1 = logf(redf[0]); const float rZ2 = 1.0f / redg[0];
  __syncthreads();

  float kl = 0.0f;
  __half w16[32];
#pragma unroll
  for (int i = 0; i < 32; ++i) {
    float q = __expf(lv[i] - M1 - lZ1);
    kl += q * __logf(q * 8192.0f + 1e-10f);
    w16[i] = __float2half_rn(__expf(yv[i] - M2) * rZ2);
  }
  {
    __half* wp = g_w16 + (size_t)row * NCODES + t * 32;
#pragma unroll
    for (int j = 0; j < 4; ++j) ((uint4*)wp)[j] = ((const uint4*)w16)[j];
  }
  redf[t] = kl;
  __syncthreads();
  for (int s = 128; s > 0; s >>= 1) { if (t < s) redf[t] += redf[t + s]; __syncthreads(); }
  if (t == 0) {
    g_kl[row] = redf[0];
    out[CODES_OFF + row] = (float)AM;
    if (GAP < GAP_THR) g_fixrows[atomicAdd(&g_fixn, 1)] = row;
  }
}

// ---------------- exact fp32 rescore for near-tie rows ----------------------
__global__ __launch_bounds__(256) void fixup_kernel(const float* __restrict__ z,
                                                    const float* __restrict__ cb,
                                                    float* __restrict__ out)
{
  __shared__ float zs[256]; __shared__ float rv[256]; __shared__ int ri[256];
  const int t = threadIdx.x;
  const int nfix = g_fixn;
  for (int e = blockIdx.x; e < nfix; e += gridDim.x) {
    const int row = g_fixrows[e];
    zs[t] = z[(size_t)row * DIM + t];
    __syncthreads();
    float best = -CUDART_INF_F; int bi = 0;
    for (int c = t; c < NCODES; c += 256) {
      const float* cp = cb + (size_t)c * DIM;
      float s = 0.0f;
#pragma unroll 8
      for (int k = 0; k < DIM; ++k) s = fmaf(zs[k], cp[k], s);
      if (s > best) { best = s; bi = c; }
    }
    rv[t] = best; ri[t] = bi;
    __syncthreads();
    for (int s = 128; s > 0; s >>= 1) {
      if (t < s) {
        float v = rv[t + s]; int vi = ri[t + s];
        if (v > rv[t] || (v == rv[t] && vi < ri[t])) { rv[t] = v; ri[t] = vi; }
      }
      __syncthreads();
    }
    if (t == 0) out[CODES_OFF + row] = (float)ri[0];
    __syncthreads();
  }
}

// ---------------- finalize losses ------------------------------------------
__global__ __launch_bounds__(256) void finalize_kernel(float* __restrict__ out)
{
  __shared__ double red[256];
  const int t = threadIdx.x;
  red[t] = g_part[t];
  __syncthreads();
  for (int s = 128; s > 0; s >>= 1) { if (t < s) red[t] += red[t + s]; __syncthreads(); }
  const double commit_sum = red[0];
  __syncthreads();
  double ks = 0.0;
  for (int i = t; i < NROWS; i += 256) ks += (double)g_kl[i];
  red[t] = ks;
  __syncthreads();
  for (int s = 128; s > 0; s >>= 1) { if (t < s) red[t] += red[t + s]; __syncthreads(); }
  if (t == 0) {
    float commit = 0.25f * (float)(commit_sum / (double)ZQ_ELEMS);
    float klm    = 0.01f * (float)(red[0] / (double)NROWS);
    out[LOSS_OFF] = commit + klm;
  }
}

// ---------------- launch ----------------------------------------------------
extern "C" void kernel_launch(void* const* d_in, const int* in_sizes, int n_in,
                              void* d_out, int out_size)
{
  const float* z  = (const float*)d_in[0];
  const float* cb = (const float*)d_in[1];
  float* out = (float*)d_out;

  void *pl, *pw, *pzh, *pzl, *pch, *pcl, *pcth, *pctl, *ppart;
  cudaGetSymbolAddress(&pl, g_logits);
  cudaGetSymbolAddress(&pw, g_w16);
  cudaGetSymbolAddress(&pzh, g_zh);
  cudaGetSymbolAddress(&pzl, g_zl);
  cudaGetSymbolAddress(&pch, g_ch);
  cudaGetSymbolAddress(&pcl, g_cl);
  cudaGetSymbolAddress(&pcth, g_cth);
  cudaGetSymbolAddress(&pctl, g_ctl);
  cudaGetSymbolAddress(&ppart, g_part);

  cudaFuncSetAttribute(gemm_hmma_kernel<3, 0>,
                       cudaFuncAttributeMaxDynamicSharedMemorySize, GEMM_SMEM);
  cudaFuncSetAttribute(gemm_hmma_kernel<2, 1>,
                       cudaFuncAttributeMaxDynamicSharedMemorySize, GEMM_SMEM);

  conv_z_kernel<<<ZQ_ELEMS / 256, 256>>>(z);            // launch 1
  conv_cb_kernel<<<(NCODES * DIM) / 256, 256>>>(cb);    // launch 2
  init_kernel<<<1, 1>>>();                              // launch 3

  // launch 4 (ncu-profiled slot): GEMM1 logits = zh*ch + zh*cl + zl*ch, bf16
  dim3 g1(NCODES / 128, NROWS / 128);
  gemm_hmma_kernel<3, 0><<<g1, 256, GEMM_SMEM>>>(
      (const uint16_t*)pzh, (const uint16_t*)pzh, (const uint16_t*)pzl,
      (const uint16_t*)pch, (const uint16_t*)pcl, (const uint16_t*)pch,
      (float*)pl, NCODES, DIM, nullptr, nullptr);

  row_kernel<<<NROWS, 256>>>(out);                      // launch 5

  // launch 6: GEMM2 z_q = w16*cth + w16*ctl, fp16, fused ST + commit
  dim3 g2(DIM / 128, NROWS / 128);
  gemm_hmma_kernel<2, 1><<<g2, 256, GEMM_SMEM>>>(
      (const uint16_t*)pw, (const uint16_t*)pw, (const uint16_t*)pw,
      (const uint16_t*)pcth, (const uint16_t*)pctl, (const uint16_t*)pcth,
      out, DIM, NCODES, z, (double*)ppart);

  fixup_kernel<<<128, 256>>>(z, cb, out);               // launch 7
  finalize_kernel<<<1, 256>>>(out);                     // launch 8
}